// round 1
// baseline (speedup 1.0000x reference)
#include <cuda_runtime.h>
#include <cuda_bf16.h>
#include <cstddef>

// LengthRegulator: out[b, t, :] = x[b, idx(b,t), :] where idx is the first j
// with cumsum(durations[b])[j] > t; zeros for t past the total length.
//
// B=16, S=512 fixed by the problem; H and T derived from sizes so the
// max_len scalar input never needs a host-side read (graph-capture safe).

#define LR_B 16
#define LR_S 512
#define LR_BLK 512        // threads per block (== S for the scan)
#define LR_FPB 64         // frames handled per block

__global__ __launch_bounds__(LR_BLK)
void LengthRegulator_15839839388014_kernel(
    const float* __restrict__ x,     // [B, S, H]
    const int*   __restrict__ dur,   // [B, S]
    float*       __restrict__ out,   // [B, T, H]
    int H, int T)
{
    __shared__ int cum[LR_S];
    __shared__ int idx_sh[LR_FPB];

    const int b   = blockIdx.y;
    const int f0  = blockIdx.x * LR_FPB;
    const int tid = threadIdx.x;

    // ---- inclusive scan of durations[b, :] (Hillis-Steele, 9 steps) ----
    cum[tid] = dur[b * LR_S + tid];
    __syncthreads();
#pragma unroll
    for (int off = 1; off < LR_S; off <<= 1) {
        int add = (tid >= off) ? cum[tid - off] : 0;
        __syncthreads();
        cum[tid] += add;
        __syncthreads();
    }

    // ---- binary search: first j with cum[j] > t (searchsorted right) ----
    if (tid < LR_FPB) {
        int t = f0 + tid;
        int lo = 0, hi = LR_S;
        while (lo < hi) {
            int mid = (lo + hi) >> 1;
            if (cum[mid] <= t) lo = mid + 1; else hi = mid;
        }
        idx_sh[tid] = lo;   // == LR_S when frame is past total length
    }
    __syncthreads();

    // ---- copy rows: 4 groups x 128 threads; one 2KB frame per group ----
    const int grp  = tid >> 7;        // 0..3
    const int lane = tid & 127;       // 0..127
    const int vecs = H >> 2;          // float4 per row (128 for H=512)

    for (int fi = grp; fi < LR_FPB; fi += 4) {
        int t = f0 + fi;
        if (t >= T) continue;
        int idx = idx_sh[fi];
        float4* dst = reinterpret_cast<float4*>(
            out + ((size_t)b * T + t) * (size_t)H);
        if (idx < LR_S) {
            const float4* src = reinterpret_cast<const float4*>(
                x + ((size_t)b * LR_S + idx) * (size_t)H);
            for (int j = lane; j < vecs; j += 128)
                dst[j] = src[j];
        } else {
            float4 z = make_float4(0.f, 0.f, 0.f, 0.f);
            for (int j = lane; j < vecs; j += 128)
                dst[j] = z;
        }
    }
}

extern "C" void kernel_launch(void* const* d_in, const int* in_sizes, int n_in,
                              void* d_out, int out_size)
{
    const float* x   = (const float*)d_in[0];
    const int*   dur = (const int*)d_in[1];
    float*       out = (float*)d_out;

    // Derive H and T from sizes; B/S are fixed by the problem shape.
    const int BS = in_sizes[1];              // B * S = 8192
    const int H  = in_sizes[0] / BS;         // 512
    const int T  = out_size / (LR_B * H);    // max_len = 4096

    dim3 grid((T + LR_FPB - 1) / LR_FPB, LR_B);
    LengthRegulator_15839839388014_kernel<<<grid, LR_BLK>>>(x, dur, out, H, T);
}

// round 2
// speedup vs baseline: 1.1237x; 1.1237x over previous
#include <cuda_runtime.h>
#include <cuda_bf16.h>
#include <cstddef>

// LengthRegulator, two-phase:
//  K1: per-batch inclusive scan of durations + searchsorted -> flat source-row
//      table g_src[b*T + t] = b*S + idx (or -1 for frames past total length).
//  K2: pure float4 gather-copy, 4 independent vec4s per thread for MLP.
//
// B=16, S=512, H=512 fixed by the problem; T derived from out_size.

#define LR_B   16
#define LR_S   512
#define LR_TM  8192          // max T the scratch table supports (T=4096 here)

__device__ int g_src[LR_B * LR_TM];

// ---------------- Kernel 1: build source-row table ----------------
__global__ __launch_bounds__(512)
void lr_index_kernel(const int* __restrict__ dur, int T)
{
    __shared__ int cum[LR_S];

    const int b   = blockIdx.y;
    const int f0  = blockIdx.x * 512;
    const int tid = threadIdx.x;

    // inclusive scan of durations[b, :]
    cum[tid] = dur[b * LR_S + tid];
    __syncthreads();
#pragma unroll
    for (int off = 1; off < LR_S; off <<= 1) {
        int add = (tid >= off) ? cum[tid - off] : 0;
        __syncthreads();
        cum[tid] += add;
        __syncthreads();
    }

    // searchsorted(right): first j with cum[j] > t
    int t = f0 + tid;
    if (t < T) {
        int lo = 0, hi = LR_S;
        while (lo < hi) {
            int mid = (lo + hi) >> 1;
            if (cum[mid] <= t) lo = mid + 1; else hi = mid;
        }
        g_src[b * T + t] = (lo < LR_S) ? (b * LR_S + lo) : -1;
    }
}

// ---------------- Kernel 2: gather-copy (H == 512 fast path) ----------------
// Flat view: output has Vtot = B*T*128 float4s. Thread handles 4 vec4s,
// block of 256 threads covers 1024 consecutive vec4s = 8 contiguous frames.
__global__ __launch_bounds__(256)
void lr_copy_kernel(const float4* __restrict__ x4,
                    float4*       __restrict__ out4,
                    size_t Vtot)
{
    const size_t base = (size_t)blockIdx.x * 1024 + threadIdx.x;

    float4 v[4];
    size_t dst[4];
#pragma unroll
    for (int k = 0; k < 4; k++) {
        size_t p = base + (size_t)k * 256;
        dst[k] = p;
        v[k] = make_float4(0.f, 0.f, 0.f, 0.f);
        if (p < Vtot) {
            int frame = (int)(p >> 7);        // / 128 vec4 per frame
            int e     = (int)(p & 127);
            int row   = g_src[frame];
            if (row >= 0)
                v[k] = __ldg(&x4[(size_t)row * 128 + e]);
        }
    }
#pragma unroll
    for (int k = 0; k < 4; k++)
        if (dst[k] < Vtot) out4[dst[k]] = v[k];
}

// ---------------- generic fallback (any H, unused for this shape) ----------
__global__ void lr_copy_generic(const float* __restrict__ x,
                                float* __restrict__ out,
                                int H, size_t total)
{
    size_t i = (size_t)blockIdx.x * blockDim.x + threadIdx.x;
    if (i >= total) return;
    int frame = (int)(i / H);
    int e     = (int)(i % H);
    int row   = g_src[frame];
    out[i] = (row >= 0) ? x[(size_t)row * H + e] : 0.f;
}

extern "C" void kernel_launch(void* const* d_in, const int* in_sizes, int n_in,
                              void* d_out, int out_size)
{
    const float* x   = (const float*)d_in[0];
    const int*   dur = (const int*)d_in[1];
    float*       out = (float*)d_out;

    const int BS = in_sizes[1];              // B * S = 8192
    const int H  = in_sizes[0] / BS;         // 512
    const int T  = out_size / (LR_B * H);    // 4096

    // K1: index table
    dim3 g1((T + 511) / 512, LR_B);
    lr_index_kernel<<<g1, 512>>>(dur, T);

    // K2: copy
    if (H == 512) {
        size_t Vtot = (size_t)out_size >> 2;             // float4 count
        int blocks  = (int)((Vtot + 1023) / 1024);
        lr_copy_kernel<<<blocks, 256>>>((const float4*)x, (float4*)out, Vtot);
    } else {
        size_t total = (size_t)out_size;
        int blocks   = (int)((total + 255) / 256);
        lr_copy_generic<<<blocks, 256>>>(x, out, H, total);
    }
}